// round 11
// baseline (speedup 1.0000x reference)
#include <cuda_runtime.h>
#include <cuda_fp16.h>
#include <cstdint>

typedef unsigned long long ull;

// ---------- packed f32x2 helpers (attention) ----------
__device__ __forceinline__ ull fma2(ull a, ull b, ull c) {
    ull d; asm("fma.rn.f32x2 %0, %1, %2, %3;" : "=l"(d) : "l"(a), "l"(b), "l"(c)); return d;
}
__device__ __forceinline__ ull add2(ull a, ull b) {
    ull d; asm("add.rn.f32x2 %0, %1, %2;" : "=l"(d) : "l"(a), "l"(b)); return d;
}
__device__ __forceinline__ ull mul2(ull a, ull b) {
    ull d; asm("mul.rn.f32x2 %0, %1, %2;" : "=l"(d) : "l"(a), "l"(b)); return d;
}
__device__ __forceinline__ ull pk(float lo, float hi) {
    ull r; asm("mov.b64 %0, {%1, %2};" : "=l"(r) : "f"(lo), "f"(hi)); return r;
}
__device__ __forceinline__ void upk(ull v, float& lo, float& hi) {
    asm("mov.b64 {%0, %1}, %2;" : "=f"(lo), "=f"(hi) : "l"(v));
}

// ---------- warp-MMA primitives (family-portable) ----------
#define SWZ(o) ((uint32_t)(o) ^ ((((uint32_t)(o)) >> 3) & 0x70u))

__device__ __forceinline__ uint32_t smem_u32(const void* p) {
    uint32_t a;
    asm("{ .reg .u64 t; cvta.to.shared.u64 t, %1; cvt.u32.u64 %0, t; }" : "=r"(a) : "l"(p));
    return a;
}
__device__ __forceinline__ void cp16(uint32_t dst, const void* src, uint32_t srcsz) {
    asm volatile("cp.async.ca.shared.global [%0], [%1], 16, %2;"
                 :: "r"(dst), "l"(src), "r"(srcsz) : "memory");
}
#define CP_COMMIT asm volatile("cp.async.commit_group;" ::: "memory")
#define CP_WAIT1  asm volatile("cp.async.wait_group 1;" ::: "memory")
#define CP_WAIT0  asm volatile("cp.async.wait_group 0;" ::: "memory")

#define LDSM4(d, a) \
    asm volatile("ldmatrix.sync.aligned.m8n8.x4.shared.b16 {%0,%1,%2,%3}, [%4];" \
                 : "=r"((d)[0]), "=r"((d)[1]), "=r"((d)[2]), "=r"((d)[3]) : "r"(a))

// main term: fp16 inputs, fp32 accumulator
#define MMA_F32(c, a, b0, b1) \
    asm volatile("mma.sync.aligned.m16n8k16.row.col.f32.f16.f16.f32 " \
                 "{%0,%1,%2,%3},{%4,%5,%6,%7},{%8,%9},{%0,%1,%2,%3};" \
                 : "+f"((c)[0]), "+f"((c)[1]), "+f"((c)[2]), "+f"((c)[3]) \
                 : "r"((a)[0]), "r"((a)[1]), "r"((a)[2]), "r"((a)[3]), \
                   "r"(b0), "r"(b1))

// correction terms: fp16 inputs, fp16 accumulator (values are ~2^-12 of main)
#define MMA_F16(c2, a, b0, b1) \
    asm volatile("mma.sync.aligned.m16n8k16.row.col.f16.f16.f16.f16 " \
                 "{%0,%1},{%2,%3,%4,%5},{%6,%7},{%0,%1};" \
                 : "+r"((c2)[0]), "+r"((c2)[1]) \
                 : "r"((a)[0]), "r"((a)[1]), "r"((a)[2]), "r"((a)[3]), \
                   "r"(b0), "r"(b1))

// ---------- scratch (device globals) ----------
__device__ __align__(128) __half g_xh[2097152], g_xl[2097152];     // [pix][256]
__device__ __align__(128) __half g_w3h[65536],   g_w3l[65536];     // [tap][oc][cin]
__device__ __align__(128) __half g_w5h[589824],  g_w5l[589824];
__device__ __align__(128) __half g_w7h[1638400], g_w7l[1638400];
__device__ __align__(128) __half g_wph[65536],   g_wpl[65536];
__device__ __align__(128) float g_q[2097152], g_k[2097152], g_v[2097152]; // [b*256+ch][1024]
__device__ __align__(128) __half g_aoh[2097152], g_aol[2097152];   // [pix][256]

// ---------- split kernels (fp16 hi/lo) ----------
__global__ void split_x(const float* __restrict__ x,
                        __half* __restrict__ xh, __half* __restrict__ xl) {
    int i = blockIdx.x * 256 + threadIdx.x;
    float f = x[i];
    __half h = __float2half_rn(f);
    xh[i] = h;
    xl[i] = __float2half_rn(f - __half2float(h));
}
// wt[(tap*256+o)*256+i] = w[(o*256+i)*taps + tap]  (hi/lo split)
__global__ void split_w(const float* __restrict__ w,
                        __half* __restrict__ wh, __half* __restrict__ wl,
                        int taps) {
    int idx = blockIdx.x * 256 + threadIdx.x;    // grid = taps*256 blocks
    int o = (idx >> 8) & 255;
    int i = idx & 255;
    int t = idx >> 16;
    float f = w[(o * 256 + i) * taps + t];
    __half h = __float2half_rn(f);
    wh[idx] = h;
    wl[idx] = __float2half_rn(f - __half2float(h));
}

// ---------- HMMA implicit-GEMM conv (fp16 split, f16-acc corrections) ----------
// D[128 pix, 128 oc]: main Ah*Bh in f32 accum; (Ah*Bl + Al*Bh) share one f16 accum.
// SMEM per stage 64KB: Ah@0 Al@16K Bh@32K Bl@48K (SW128 rows of 128B), double buffer.
// 8 warps: warp_m = wid&3 (32 rows), warp_n = wid>>2 (64 cols).
// TROUT=true -> C[(b*256+oc)*1024 + n] (+bias), via coalescing smem stage;
// else row-major C[pix*256+oc], no bias.
template<int KS, bool TROUT>
__global__ __launch_bounds__(256, 1)
void conv_mma(const __half* __restrict__ Ah, const __half* __restrict__ Al,
              const __half* __restrict__ Bh, const __half* __restrict__ Bl,
              const float* __restrict__ bias, float* __restrict__ C)
{
    extern __shared__ char smem[];
    const uint32_t sb = smem_u32(smem);
    const int tid = threadIdx.x, wid = tid >> 5, lane = tid & 31;
    const int nb = blockIdx.x;      // oc block of 128 (0..1)
    const int mb = blockIdx.y;      // pixel block of 128 (0..63)
    const int p0 = mb * 128, bimg = p0 >> 10;
    const int wm = (wid & 3) * 32, wn = (wid >> 2) * 64;

    float acc[2][8][4];
    uint32_t acc16[2][8][2];
#pragma unroll
    for (int mi = 0; mi < 2; ++mi)
#pragma unroll
        for (int n8 = 0; n8 < 8; ++n8) {
#pragma unroll
            for (int e = 0; e < 4; ++e) acc[mi][n8][e] = 0.f;
            acc16[mi][n8][0] = 0u; acc16[mi][n8][1] = 0u;
        }

    const int T = KS * KS * 4;      // stages = taps x 4 channel-chunks of 64

    auto stage = [&](int it) {
        const int tap = it >> 2, kc = it & 3;
        const int dy = tap / KS - KS / 2, dx = tap % KS - KS / 2;
        const uint32_t bs = sb + (uint32_t)(it & 1) * 65536u;
#pragma unroll
        for (int pass = 0; pass < 4; ++pass) {
            const int idx = pass * 256 + tid;       // 0..1023
            const int r = idx >> 3, gran = idx & 7; // row 0..127, 16B granule
            const uint32_t so = SWZ(r * 128 + gran * 16);
            // A (pixel row shifted by tap; zfill out-of-image)
            const int p = p0 + r;
            const int py = ((p >> 5) & 31) + dy, px = (p & 31) + dx;
            const bool v = ((unsigned)py < 32u) && ((unsigned)px < 32u);
            const size_t aoff = v ?
                ((size_t)((((bimg * 32 + py) << 5) + px)) * 256 + (size_t)kc * 64) * 2
                + (size_t)gran * 16 : 0;
            const uint32_t sz = v ? 16u : 0u;
            cp16(bs + so,         (const char*)Ah + aoff, sz);
            cp16(bs + 16384 + so, (const char*)Al + aoff, sz);
            // B (always valid)
            const size_t boff =
                ((size_t)(tap * 256 + nb * 128 + r) * 256 + (size_t)kc * 64) * 2
                + (size_t)gran * 16;
            cp16(bs + 32768 + so, (const char*)Bh + boff, 16u);
            cp16(bs + 49152 + so, (const char*)Bl + boff, 16u);
        }
    };

    stage(0); CP_COMMIT;

#pragma unroll 1
    for (int it = 0; it < T; ++it) {
        if (it + 1 < T) { stage(it + 1); CP_COMMIT; CP_WAIT1; }
        else            { CP_WAIT0; }
        __syncthreads();

        const uint32_t bs = sb + (uint32_t)(it & 1) * 65536u;
#pragma unroll
        for (int kk = 0; kk < 4; ++kk) {
            const int kb = kk * 32;                 // 16 fp16 = 32B
            uint32_t ahf[2][4], alf[2][4], bhf[4][4], blf[4][4];
#pragma unroll
            for (int mi = 0; mi < 2; ++mi) {
                const int r = wm + mi * 16 + (lane & 15);
                const int cb = kb + ((lane >> 4) << 4);
                const uint32_t ad = bs + SWZ(r * 128 + cb);
                LDSM4(ahf[mi], ad);
                LDSM4(alf[mi], ad + 16384);
            }
#pragma unroll
            for (int q = 0; q < 4; ++q) {
                const int r = wn + q * 16 + (lane & 7) + ((lane & 16) >> 1);
                const int cb = kb + ((lane & 8) << 1);
                const uint32_t bd = bs + 32768 + SWZ(r * 128 + cb);
                LDSM4(bhf[q], bd);
                LDSM4(blf[q], bd + 16384);
            }
            // main term (f32 accum)
#pragma unroll
            for (int mi = 0; mi < 2; ++mi)
#pragma unroll
                for (int n8 = 0; n8 < 8; ++n8)
                    MMA_F32(acc[mi][n8], ahf[mi],
                            bhf[n8 >> 1][(n8 & 1) * 2], bhf[n8 >> 1][(n8 & 1) * 2 + 1]);
            // correction terms (shared f16 accum)
#pragma unroll
            for (int mi = 0; mi < 2; ++mi)
#pragma unroll
                for (int n8 = 0; n8 < 8; ++n8)
                    MMA_F16(acc16[mi][n8], ahf[mi],
                            blf[n8 >> 1][(n8 & 1) * 2], blf[n8 >> 1][(n8 & 1) * 2 + 1]);
#pragma unroll
            for (int mi = 0; mi < 2; ++mi)
#pragma unroll
                for (int n8 = 0; n8 < 8; ++n8)
                    MMA_F16(acc16[mi][n8], alf[mi],
                            bhf[n8 >> 1][(n8 & 1) * 2], bhf[n8 >> 1][(n8 & 1) * 2 + 1]);
        }
        __syncthreads();
    }

    // combine main + corrections
    float tot[2][8][4];
#pragma unroll
    for (int mi = 0; mi < 2; ++mi)
#pragma unroll
        for (int n8 = 0; n8 < 8; ++n8) {
            __half2 c01 = *(__half2*)&acc16[mi][n8][0];
            __half2 c23 = *(__half2*)&acc16[mi][n8][1];
            tot[mi][n8][0] = acc[mi][n8][0] + __low2float(c01);
            tot[mi][n8][1] = acc[mi][n8][1] + __high2float(c01);
            tot[mi][n8][2] = acc[mi][n8][2] + __low2float(c23);
            tot[mi][n8][3] = acc[mi][n8][3] + __high2float(c23);
        }

    // epilogue: D fragment c0=(g,2t) c1=(g,2t+1) c2=(g+8,2t) c3=(g+8,2t+1)
    const int g = lane >> 2, t2 = (lane & 3) * 2;
    if (TROUT) {
        // stage through smem [oc 128][pix 128] stride 132 (conflict-free), then
        // copy out channel-major rows (512B contiguous) coalesced.
        float* fs = (float*)smem;
#pragma unroll
        for (int mi = 0; mi < 2; ++mi)
#pragma unroll
            for (int n8 = 0; n8 < 8; ++n8) {
                const int cl = wn + n8 * 8 + t2;
                const int r0 = wm + mi * 16 + g;
                fs[(size_t)cl * 132 + r0]            = tot[mi][n8][0];
                fs[(size_t)(cl + 1) * 132 + r0]      = tot[mi][n8][1];
                fs[(size_t)cl * 132 + r0 + 8]        = tot[mi][n8][2];
                fs[(size_t)(cl + 1) * 132 + r0 + 8]  = tot[mi][n8][3];
            }
        __syncthreads();
        const int row = tid >> 1;                  // local oc 0..127
        const int half = (tid & 1) * 64;
        const int c = nb * 128 + row;
        const float bv = bias[c];
        const int n0 = (p0 & 1023) + half;
        float* dst = C + (((size_t)(bimg * 256 + c)) << 10) + n0;
        const float* srcr = fs + (size_t)row * 132 + half;
#pragma unroll
        for (int j = 0; j < 16; ++j) {
            float4 v4 = *(const float4*)(srcr + j * 4);
            *(float4*)(dst + j * 4) =
                make_float4(v4.x + bv, v4.y + bv, v4.z + bv, v4.w + bv);
        }
    } else {
#pragma unroll
        for (int mi = 0; mi < 2; ++mi)
#pragma unroll
            for (int n8 = 0; n8 < 8; ++n8) {
                const int c = nb * 128 + wn + n8 * 8 + t2;
                const int r0 = p0 + wm + mi * 16 + g;
                *(float2*)(C + (size_t)r0 * 256 + c) =
                    make_float2(tot[mi][n8][0], tot[mi][n8][1]);
                *(float2*)(C + (size_t)(r0 + 8) * 256 + c) =
                    make_float2(tot[mi][n8][2], tot[mi][n8][3]);
            }
    }
}

// ---------- attention (f32x2; exp2-domain scores; emits fp16 hi/lo) ----------
__global__ __launch_bounds__(512, 1)
void attn_kernel(const float* __restrict__ qT, const float* __restrict__ kT,
                 const float* __restrict__ vT,
                 __half* __restrict__ aoh, __half* __restrict__ aol)
{
    extern __shared__ float sm[];
    float* Ks = sm;            // [1024][16]
    float* Vs = sm + 16384;    // [1024][16]
    __shared__ int s_maxn;

    const int bh = blockIdx.x;
    const int b = bh >> 4, a = bh & 15;
    const int tid = threadIdx.x;

    const float* kb = kT + ((b * 256 + a * 16) << 10);
    const float* vb = vT + ((b * 256 + a * 16) << 10);
    const float* qslab = qT + ((b * 256 + a * 16) << 10);

    for (int i = tid; i < 4096; i += 512) {
        ((float4*)Ks)[i] = ((const float4*)kb)[i];
        ((float4*)Vs)[i] = ((const float4*)vb)[i];
    }
    if (tid == 0) s_maxn = 0;
    __syncthreads();

    float mx = 0.f;
    for (int t = tid; t < 1024; t += 512) {
        const float* kr = Ks + t * 16;
        float s = 0.f;
#pragma unroll
        for (int d = 0; d < 16; ++d) s = fmaf(kr[d], kr[d], s);
        mx = fmaxf(mx, s);
    }
#pragma unroll
    for (int off = 16; off; off >>= 1) mx = fmaxf(mx, __shfl_xor_sync(0xffffffffu, mx, off));
    if ((tid & 31) == 0) atomicMax(&s_maxn, __float_as_int(mx));
    __syncthreads();
    const float kn = sqrtf(__int_as_float(s_maxn));

    for (int qi = 0; qi < 2; ++qi) {
        const int t = qi * 512 + tid;

        ull q2[8];
        {
            const ulonglong2* qp = (const ulonglong2*)(qslab + t * 16);
            ulonglong2 u0 = qp[0], u1 = qp[1], u2 = qp[2], u3 = qp[3];
            q2[0] = u0.x; q2[1] = u0.y; q2[2] = u1.x; q2[3] = u1.y;
            q2[4] = u2.x; q2[5] = u2.y; q2[6] = u3.x; q2[7] = u3.y;
        }
        // fold 0.25 * log2(e) into q: scores live in exp2 domain
        const float QS = 0.25f * 1.4426950408889634f;
        const ull qs = pk(QS, QS);
#pragma unroll
        for (int j = 0; j < 8; ++j) q2[j] = mul2(q2[j], qs);

        ull n0 = 0ull, n1 = 0ull;
#pragma unroll
        for (int j = 0; j < 8; j += 2) {
            n0 = fma2(q2[j], q2[j], n0);
            n1 = fma2(q2[j + 1], q2[j + 1], n1);
        }
        n0 = add2(n0, n1);
        float nl, nh; upk(n0, nl, nh);
        const float M = sqrtf(nl + nh) * kn;   // Cauchy-Schwarz bound in exp2 domain

        ull acc[8];
#pragma unroll
        for (int j = 0; j < 8; ++j) acc[j] = 0ull;
        float l = 0.f;

#pragma unroll 2
        for (int m = 0; m < 1024; ++m) {
            const ulonglong2* kp = (const ulonglong2*)(Ks + m * 16);
            ulonglong2 k0 = kp[0], k1 = kp[1], k2 = kp[2], k3 = kp[3];
            ull c0 = 0ull, c1 = 0ull;
            c0 = fma2(q2[0], k0.x, c0); c1 = fma2(q2[1], k0.y, c1);
            c0 = fma2(q2[2], k1.x, c0); c1 = fma2(q2[3], k1.y, c1);
            c0 = fma2(q2[4], k2.x, c0); c1 = fma2(q2[5], k2.y, c1);
            c0 = fma2(q2[6], k3.x, c0); c1 = fma2(q2[7], k3.y, c1);
            c0 = add2(c0, c1);
            float sl, sh; upk(c0, sl, sh);
            const float p = exp2f(sl + sh - M);   // arg <= 0, no overflow
            l += p;

            const ulonglong2* vp = (const ulonglong2*)(Vs + m * 16);
            ulonglong2 v0 = vp[0], v1 = vp[1], v2 = vp[2], v3 = vp[3];
            const ull pp = pk(p, p);
            acc[0] = fma2(pp, v0.x, acc[0]); acc[1] = fma2(pp, v0.y, acc[1]);
            acc[2] = fma2(pp, v1.x, acc[2]); acc[3] = fma2(pp, v1.y, acc[3]);
            acc[4] = fma2(pp, v2.x, acc[4]); acc[5] = fma2(pp, v2.y, acc[5]);
            acc[6] = fma2(pp, v3.x, acc[6]); acc[7] = fma2(pp, v3.y, acc[7]);
        }

        const float inv = 1.f / l;
        float o[16];
#pragma unroll
        for (int j = 0; j < 8; ++j) upk(acc[j], o[2 * j], o[2 * j + 1]);
        const size_t base = ((size_t)((b << 10) + t)) * 256 + a * 16;
        __half2* dh = (__half2*)(aoh + base);
        __half2* dl = (__half2*)(aol + base);
#pragma unroll
        for (int j = 0; j < 8; ++j) {
            float v0 = o[2 * j] * inv, v1 = o[2 * j + 1] * inv;
            __half h0 = __float2half_rn(v0), h1 = __float2half_rn(v1);
            __half l0 = __float2half_rn(v0 - __half2float(h0));
            __half l1 = __float2half_rn(v1 - __half2float(h1));
            dh[j] = __halves2half2(h0, h1);
            dl[j] = __halves2half2(l0, l1);
        }
    }
}

// ---------- launch ----------
extern "C" void kernel_launch(void* const* d_in, const int* in_sizes, int n_in,
                              void* d_out, int out_size)
{
    (void)in_sizes; (void)out_size;
    if (n_in < 8) return;

    const float* x  = (const float*)d_in[0];
    const float* w3 = (const float*)d_in[1];
    const float* b3 = (const float*)d_in[2];
    const float* w5 = (const float*)d_in[3];
    const float* b5 = (const float*)d_in[4];
    const float* w7 = (const float*)d_in[5];
    const float* b7 = (const float*)d_in[6];
    const float* wp = (const float*)d_in[7];
    float* out = (float*)d_out;

    __half *p_xh, *p_xl, *p_w3h, *p_w3l, *p_w5h, *p_w5l, *p_w7h, *p_w7l,
           *p_wph, *p_wpl, *p_aoh, *p_aol;
    float *p_q, *p_k, *p_v;
    cudaGetSymbolAddress((void**)&p_xh,  g_xh);  cudaGetSymbolAddress((void**)&p_xl,  g_xl);
    cudaGetSymbolAddress((void**)&p_w3h, g_w3h); cudaGetSymbolAddress((void**)&p_w3l, g_w3l);
    cudaGetSymbolAddress((void**)&p_w5h, g_w5h); cudaGetSymbolAddress((void**)&p_w5l, g_w5l);
    cudaGetSymbolAddress((void**)&p_w7h, g_w7h); cudaGetSymbolAddress((void**)&p_w7l, g_w7l);
    cudaGetSymbolAddress((void**)&p_wph, g_wph); cudaGetSymbolAddress((void**)&p_wpl, g_wpl);
    cudaGetSymbolAddress((void**)&p_aoh, g_aoh); cudaGetSymbolAddress((void**)&p_aol, g_aol);
    cudaGetSymbolAddress((void**)&p_q, g_q);
    cudaGetSymbolAddress((void**)&p_k, g_k);
    cudaGetSymbolAddress((void**)&p_v, g_v);

    const int CONV_SMEM = 2 * 65536;   // 128 KB (double-buffered stages; also epilogue stage)
    cudaFuncSetAttribute(conv_mma<1, true>,  cudaFuncAttributeMaxDynamicSharedMemorySize, CONV_SMEM);
    cudaFuncSetAttribute(conv_mma<3, true>,  cudaFuncAttributeMaxDynamicSharedMemorySize, CONV_SMEM);
    cudaFuncSetAttribute(conv_mma<5, true>,  cudaFuncAttributeMaxDynamicSharedMemorySize, CONV_SMEM);
    cudaFuncSetAttribute(conv_mma<1, false>, cudaFuncAttributeMaxDynamicSharedMemorySize, CONV_SMEM);
    cudaFuncSetAttribute(attn_kernel, cudaFuncAttributeMaxDynamicSharedMemorySize, 131072);

    // fp16 hi/lo splits
    split_x<<<8192, 256>>>(x, p_xh, p_xl);
    split_w<<<1 * 256, 256>>>(w3, p_w3h, p_w3l, 1);
    split_w<<<9 * 256, 256>>>(w5, p_w5h, p_w5l, 9);
    split_w<<<25 * 256, 256>>>(w7, p_w7h, p_w7l, 25);
    split_w<<<1 * 256, 256>>>(wp, p_wph, p_wpl, 1);

    dim3 grid(2, 64);
    // q: 1x1 (w3), v: 3x3 (w5), k: 5x5 (w7) — names match the reference
    conv_mma<1, true><<<grid, 256, CONV_SMEM>>>(p_xh, p_xl, p_w3h, p_w3l, b3, p_q);
    conv_mma<3, true><<<grid, 256, CONV_SMEM>>>(p_xh, p_xl, p_w5h, p_w5l, b5, p_v);
    conv_mma<5, true><<<grid, 256, CONV_SMEM>>>(p_xh, p_xl, p_w7h, p_w7l, b7, p_k);

    attn_kernel<<<128, 512, 131072>>>(p_q, p_k, p_v, p_aoh, p_aol);

    conv_mma<1, false><<<grid, 256, CONV_SMEM>>>(p_aoh, p_aol, p_wph, p_wpl, nullptr, out);
}

// round 14
// speedup vs baseline: 1.6154x; 1.6154x over previous
#include <cuda_runtime.h>
#include <cuda_bf16.h>
#include <cstdint>

typedef unsigned long long ull;

// ---------- packed f32x2 helpers (attention) ----------
__device__ __forceinline__ ull fma2(ull a, ull b, ull c) {
    ull d; asm("fma.rn.f32x2 %0, %1, %2, %3;" : "=l"(d) : "l"(a), "l"(b), "l"(c)); return d;
}
__device__ __forceinline__ ull add2(ull a, ull b) {
    ull d; asm("add.rn.f32x2 %0, %1, %2;" : "=l"(d) : "l"(a), "l"(b)); return d;
}
__device__ __forceinline__ ull mul2(ull a, ull b) {
    ull d; asm("mul.rn.f32x2 %0, %1, %2;" : "=l"(d) : "l"(a), "l"(b)); return d;
}
__device__ __forceinline__ ull pk(float lo, float hi) {
    ull r; asm("mov.b64 %0, {%1, %2};" : "=l"(r) : "f"(lo), "f"(hi)); return r;
}
__device__ __forceinline__ void upk(ull v, float& lo, float& hi) {
    asm("mov.b64 {%0, %1}, %2;" : "=f"(lo), "=f"(hi) : "l"(v));
}

// ---------- warp-MMA primitives (family-portable) ----------
#define SWZ(o) ((uint32_t)(o) ^ ((((uint32_t)(o)) >> 3) & 0x70u))

__device__ __forceinline__ uint32_t smem_u32(const void* p) {
    uint32_t a;
    asm("{ .reg .u64 t; cvta.to.shared.u64 t, %1; cvt.u32.u64 %0, t; }" : "=r"(a) : "l"(p));
    return a;
}
__device__ __forceinline__ void cp16(uint32_t dst, const void* src, uint32_t srcsz) {
    asm volatile("cp.async.ca.shared.global [%0], [%1], 16, %2;"
                 :: "r"(dst), "l"(src), "r"(srcsz) : "memory");
}
#define CP_COMMIT asm volatile("cp.async.commit_group;" ::: "memory")
#define CP_WAIT1  asm volatile("cp.async.wait_group 1;" ::: "memory")
#define CP_WAIT0  asm volatile("cp.async.wait_group 0;" ::: "memory")

#define LDSM4(d, a) \
    asm volatile("ldmatrix.sync.aligned.m8n8.x4.shared.b16 {%0,%1,%2,%3}, [%4];" \
                 : "=r"((d)[0]), "=r"((d)[1]), "=r"((d)[2]), "=r"((d)[3]) : "r"(a))

#define MMA16816(c, a, b0, b1) \
    asm volatile("mma.sync.aligned.m16n8k16.row.col.f32.bf16.bf16.f32 " \
                 "{%0,%1,%2,%3},{%4,%5,%6,%7},{%8,%9},{%0,%1,%2,%3};" \
                 : "+f"((c)[0]), "+f"((c)[1]), "+f"((c)[2]), "+f"((c)[3]) \
                 : "r"((a)[0]), "r"((a)[1]), "r"((a)[2]), "r"((a)[3]), \
                   "r"(b0), "r"(b1))

// ---------- scratch (device globals) ----------
__device__ __align__(128) __nv_bfloat16 g_xh[2097152], g_xl[2097152];     // [pix][256]
__device__ __align__(128) __nv_bfloat16 g_w3h[65536],   g_w3l[65536];     // [tap][oc][cin]
__device__ __align__(128) __nv_bfloat16 g_w5h[589824],  g_w5l[589824];
__device__ __align__(128) __nv_bfloat16 g_w7h[1638400], g_w7l[1638400];
__device__ __align__(128) __nv_bfloat16 g_wph[65536],   g_wpl[65536];
__device__ __align__(128) float g_q[2097152], g_k[2097152], g_v[2097152]; // [b*256+ch][1024]
__device__ __align__(128) __nv_bfloat16 g_aoh[2097152], g_aol[2097152];   // [pix][256]

// ---------- split kernels (bf16 hi/lo) ----------
__global__ void split_x(const float* __restrict__ x,
                        __nv_bfloat16* __restrict__ xh, __nv_bfloat16* __restrict__ xl) {
    int i = blockIdx.x * 256 + threadIdx.x;
    float f = x[i];
    __nv_bfloat16 h = __float2bfloat16(f);
    xh[i] = h;
    xl[i] = __float2bfloat16(f - __bfloat162float(h));
}
// wt[(tap*256+o)*256+i] = w[(o*256+i)*taps + tap]  (hi/lo split)
__global__ void split_w(const float* __restrict__ w,
                        __nv_bfloat16* __restrict__ wh, __nv_bfloat16* __restrict__ wl,
                        int taps) {
    int idx = blockIdx.x * 256 + threadIdx.x;    // grid = taps*256 blocks
    int o = (idx >> 8) & 255;
    int i = idx & 255;
    int t = idx >> 16;
    float f = w[(o * 256 + i) * taps + t];
    __nv_bfloat16 h = __float2bfloat16(f);
    wh[idx] = h;
    wl[idx] = __float2bfloat16(f - __bfloat162float(h));
}

// ---------- HMMA implicit-GEMM conv (bf16 3-term split, f32 accum — R9 engine) ----------
// D[128 pix, 128 oc] = sum over (tap, 64-ch chunk) of Ah*Bh + Ah*Bl + Al*Bh.
// SMEM per stage 64KB: Ah@0 Al@16K Bh@32K Bl@48K (SW128 rows of 128B), double buffer.
// 8 warps: warp_m = wid&3 (32 rows), warp_n = wid>>2 (64 cols).
// TROUT=true -> C[(b*256+oc)*1024 + n] (+bias) via coalescing smem stage;
// else row-major C[pix*256+oc], no bias.
template<int KS, bool TROUT>
__global__ __launch_bounds__(256, 1)
void conv_mma(const __nv_bfloat16* __restrict__ Ah, const __nv_bfloat16* __restrict__ Al,
              const __nv_bfloat16* __restrict__ Bh, const __nv_bfloat16* __restrict__ Bl,
              const float* __restrict__ bias, float* __restrict__ C)
{
    extern __shared__ char smem[];
    const uint32_t sb = smem_u32(smem);
    const int tid = threadIdx.x, wid = tid >> 5, lane = tid & 31;
    const int nb = blockIdx.x;      // oc block of 128 (0..1)
    const int mb = blockIdx.y;      // pixel block of 128 (0..63)
    const int p0 = mb * 128, bimg = p0 >> 10;
    const int wm = (wid & 3) * 32, wn = (wid >> 2) * 64;

    float acc[2][8][4];
#pragma unroll
    for (int mi = 0; mi < 2; ++mi)
#pragma unroll
        for (int n8 = 0; n8 < 8; ++n8)
#pragma unroll
            for (int e = 0; e < 4; ++e) acc[mi][n8][e] = 0.f;

    const int T = KS * KS * 4;      // stages = taps x 4 channel-chunks of 64

    auto stage = [&](int it) {
        const int tap = it >> 2, kc = it & 3;
        const int dy = tap / KS - KS / 2, dx = tap % KS - KS / 2;
        const uint32_t bs = sb + (uint32_t)(it & 1) * 65536u;
#pragma unroll
        for (int pass = 0; pass < 4; ++pass) {
            const int idx = pass * 256 + tid;       // 0..1023
            const int r = idx >> 3, gran = idx & 7; // row 0..127, 16B granule
            const uint32_t so = SWZ(r * 128 + gran * 16);
            // A (pixel row shifted by tap; zfill out-of-image)
            const int p = p0 + r;
            const int py = ((p >> 5) & 31) + dy, px = (p & 31) + dx;
            const bool v = ((unsigned)py < 32u) && ((unsigned)px < 32u);
            const size_t aoff = v ?
                ((size_t)((((bimg * 32 + py) << 5) + px)) * 256 + (size_t)kc * 64) * 2
                + (size_t)gran * 16 : 0;
            const uint32_t sz = v ? 16u : 0u;
            cp16(bs + so,         (const char*)Ah + aoff, sz);
            cp16(bs + 16384 + so, (const char*)Al + aoff, sz);
            // B (always valid)
            const size_t boff =
                ((size_t)(tap * 256 + nb * 128 + r) * 256 + (size_t)kc * 64) * 2
                + (size_t)gran * 16;
            cp16(bs + 32768 + so, (const char*)Bh + boff, 16u);
            cp16(bs + 49152 + so, (const char*)Bl + boff, 16u);
        }
    };

    stage(0); CP_COMMIT;

#pragma unroll 1
    for (int it = 0; it < T; ++it) {
        if (it + 1 < T) { stage(it + 1); CP_COMMIT; CP_WAIT1; }
        else            { CP_WAIT0; }
        __syncthreads();

        const uint32_t bs = sb + (uint32_t)(it & 1) * 65536u;
#pragma unroll
        for (int kk = 0; kk < 4; ++kk) {
            const int kb = kk * 32;                 // 16 bf16 = 32B
            uint32_t ahf[2][4], alf[2][4], bhf[4][4], blf[4][4];
#pragma unroll
            for (int mi = 0; mi < 2; ++mi) {
                const int r = wm + mi * 16 + (lane & 15);
                const int cb = kb + ((lane >> 4) << 4);
                const uint32_t ad = bs + SWZ(r * 128 + cb);
                LDSM4(ahf[mi], ad);
                LDSM4(alf[mi], ad + 16384);
            }
#pragma unroll
            for (int q = 0; q < 4; ++q) {
                const int r = wn + q * 16 + (lane & 7) + ((lane & 16) >> 1);
                const int cb = kb + ((lane & 8) << 1);
                const uint32_t bd = bs + 32768 + SWZ(r * 128 + cb);
                LDSM4(bhf[q], bd);
                LDSM4(blf[q], bd + 16384);
            }
            // term-major ordering: no back-to-back same-acc dependencies
#pragma unroll
            for (int mi = 0; mi < 2; ++mi)
#pragma unroll
                for (int n8 = 0; n8 < 8; ++n8)
                    MMA16816(acc[mi][n8], ahf[mi],
                             bhf[n8 >> 1][(n8 & 1) * 2], bhf[n8 >> 1][(n8 & 1) * 2 + 1]);
#pragma unroll
            for (int mi = 0; mi < 2; ++mi)
#pragma unroll
                for (int n8 = 0; n8 < 8; ++n8)
                    MMA16816(acc[mi][n8], ahf[mi],
                             blf[n8 >> 1][(n8 & 1) * 2], blf[n8 >> 1][(n8 & 1) * 2 + 1]);
#pragma unroll
            for (int mi = 0; mi < 2; ++mi)
#pragma unroll
                for (int n8 = 0; n8 < 8; ++n8)
                    MMA16816(acc[mi][n8], alf[mi],
                             bhf[n8 >> 1][(n8 & 1) * 2], bhf[n8 >> 1][(n8 & 1) * 2 + 1]);
        }
        __syncthreads();
    }

    // epilogue: D fragment c0=(g,2t) c1=(g,2t+1) c2=(g+8,2t) c3=(g+8,2t+1)
    const int g = lane >> 2, t2 = (lane & 3) * 2;
    if (TROUT) {
        // stage through smem [oc 128][pix 128] stride 132 (conflict-free), then
        // copy out channel-major rows (512B contiguous) coalesced. Verified in R11.
        float* fs = (float*)smem;
#pragma unroll
        for (int mi = 0; mi < 2; ++mi)
#pragma unroll
            for (int n8 = 0; n8 < 8; ++n8) {
                const int cl = wn + n8 * 8 + t2;
                const int r0 = wm + mi * 16 + g;
                fs[(size_t)cl * 132 + r0]            = acc[mi][n8][0];
                fs[(size_t)(cl + 1) * 132 + r0]      = acc[mi][n8][1];
                fs[(size_t)cl * 132 + r0 + 8]        = acc[mi][n8][2];
                fs[(size_t)(cl + 1) * 132 + r0 + 8]  = acc[mi][n8][3];
            }
        __syncthreads();
        const int row = tid >> 1;                  // local oc 0..127
        const int half = (tid & 1) * 64;
        const int c = nb * 128 + row;
        const float bv = bias[c];
        const int n0 = (p0 & 1023) + half;
        float* dst = C + (((size_t)(bimg * 256 + c)) << 10) + n0;
        const float* srcr = fs + (size_t)row * 132 + half;
#pragma unroll
        for (int j = 0; j < 16; ++j) {
            float4 v4 = *(const float4*)(srcr + j * 4);
            *(float4*)(dst + j * 4) =
                make_float4(v4.x + bv, v4.y + bv, v4.z + bv, v4.w + bv);
        }
    } else {
#pragma unroll
        for (int mi = 0; mi < 2; ++mi)
#pragma unroll
            for (int n8 = 0; n8 < 8; ++n8) {
                const int c = nb * 128 + wn + n8 * 8 + t2;
                const int r0 = p0 + wm + mi * 16 + g;
                *(float2*)(C + (size_t)r0 * 256 + c) =
                    make_float2(acc[mi][n8][0], acc[mi][n8][1]);
                *(float2*)(C + (size_t)(r0 + 8) * 256 + c) =
                    make_float2(acc[mi][n8][2], acc[mi][n8][3]);
            }
    }
}

// ---------- attention (f32x2; exp2-domain scores; emits bf16 hi/lo) ----------
__global__ __launch_bounds__(512, 1)
void attn_kernel(const float* __restrict__ qT, const float* __restrict__ kT,
                 const float* __restrict__ vT,
                 __nv_bfloat16* __restrict__ aoh, __nv_bfloat16* __restrict__ aol)
{
    extern __shared__ float sm[];
    float* Ks = sm;            // [1024][16]
    float* Vs = sm + 16384;    // [1024][16]
    __shared__ int s_maxn;

    const int bh = blockIdx.x;
    const int b = bh >> 4, a = bh & 15;
    const int tid = threadIdx.x;

    const float* kb = kT + ((b * 256 + a * 16) << 10);
    const float* vb = vT + ((b * 256 + a * 16) << 10);
    const float* qslab = qT + ((b * 256 + a * 16) << 10);

    for (int i = tid; i < 4096; i += 512) {
        ((float4*)Ks)[i] = ((const float4*)kb)[i];
        ((float4*)Vs)[i] = ((const float4*)vb)[i];
    }
    if (tid == 0) s_maxn = 0;
    __syncthreads();

    float mx = 0.f;
    for (int t = tid; t < 1024; t += 512) {
        const float* kr = Ks + t * 16;
        float s = 0.f;
#pragma unroll
        for (int d = 0; d < 16; ++d) s = fmaf(kr[d], kr[d], s);
        mx = fmaxf(mx, s);
    }
#pragma unroll
    for (int off = 16; off; off >>= 1) mx = fmaxf(mx, __shfl_xor_sync(0xffffffffu, mx, off));
    if ((tid & 31) == 0) atomicMax(&s_maxn, __float_as_int(mx));
    __syncthreads();
    const float kn = sqrtf(__int_as_float(s_maxn));

    for (int qi = 0; qi < 2; ++qi) {
        const int t = qi * 512 + tid;

        ull q2[8];
        {
            const ulonglong2* qp = (const ulonglong2*)(qslab + t * 16);
            ulonglong2 u0 = qp[0], u1 = qp[1], u2 = qp[2], u3 = qp[3];
            q2[0] = u0.x; q2[1] = u0.y; q2[2] = u1.x; q2[3] = u1.y;
            q2[4] = u2.x; q2[5] = u2.y; q2[6] = u3.x; q2[7] = u3.y;
        }
        // fold 0.25 * log2(e) into q: scores live in exp2 domain
        const float QS = 0.25f * 1.4426950408889634f;
        const ull qs = pk(QS, QS);
#pragma unroll
        for (int j = 0; j < 8; ++j) q2[j] = mul2(q2[j], qs);

        ull n0 = 0ull, n1 = 0ull;
#pragma unroll
        for (int j = 0; j < 8; j += 2) {
            n0 = fma2(q2[j], q2[j], n0);
            n1 = fma2(q2[j + 1], q2[j + 1], n1);
        }
        n0 = add2(n0, n1);
        float nl, nh; upk(n0, nl, nh);
        const float M = sqrtf(nl + nh) * kn;   // Cauchy-Schwarz bound in exp2 domain

        ull acc[8];
#pragma unroll
        for (int j = 0; j < 8; ++j) acc[j] = 0ull;
        float l = 0.f;

#pragma unroll 2
        for (int m = 0; m < 1024; ++m) {
            const ulonglong2* kp = (const ulonglong2*)(Ks + m * 16);
            ulonglong2 k0 = kp[0], k1 = kp[1], k2 = kp[2], k3 = kp[3];
            ull c0 = 0ull, c1 = 0ull;
            c0 = fma2(q2[0], k0.x, c0); c1 = fma2(q2[1], k0.y, c1);
            c0 = fma2(q2[2], k1.x, c0); c1 = fma2(q2[3], k1.y, c1);
            c0 = fma2(q2[4], k2.x, c0); c1 = fma2(q2[5], k2.y, c1);
            c0 = fma2(q2[6], k3.x, c0); c1 = fma2(q2[7], k3.y, c1);
            c0 = add2(c0, c1);
            float sl, sh; upk(c0, sl, sh);
            const float p = exp2f(sl + sh - M);   // arg <= 0, no overflow
            l += p;

            const ulonglong2* vp = (const ulonglong2*)(Vs + m * 16);
            ulonglong2 v0 = vp[0], v1 = vp[1], v2 = vp[2], v3 = vp[3];
            const ull pp = pk(p, p);
            acc[0] = fma2(pp, v0.x, acc[0]); acc[1] = fma2(pp, v0.y, acc[1]);
            acc[2] = fma2(pp, v1.x, acc[2]); acc[3] = fma2(pp, v1.y, acc[3]);
            acc[4] = fma2(pp, v2.x, acc[4]); acc[5] = fma2(pp, v2.y, acc[5]);
            acc[6] = fma2(pp, v3.x, acc[6]); acc[7] = fma2(pp, v3.y, acc[7]);
        }

        const float inv = 1.f / l;
        float o[16];
#pragma unroll
        for (int j = 0; j < 8; ++j) upk(acc[j], o[2 * j], o[2 * j + 1]);
        const size_t base = ((size_t)((b << 10) + t)) * 256 + a * 16;
        __nv_bfloat162* dh = (__nv_bfloat162*)(aoh + base);
        __nv_bfloat162* dl = (__nv_bfloat162*)(aol + base);
#pragma unroll
        for (int j = 0; j < 8; ++j) {
            float v0 = o[2 * j] * inv, v1 = o[2 * j + 1] * inv;
            __nv_bfloat16 h0 = __float2bfloat16(v0), h1 = __float2bfloat16(v1);
            __nv_bfloat16 l0 = __float2bfloat16(v0 - __bfloat162float(h0));
            __nv_bfloat16 l1 = __float2bfloat16(v1 - __bfloat162float(h1));
            dh[j] = __halves2bfloat162(h0, h1);
            dl[j] = __halves2bfloat162(l0, l1);
        }
    }
}

// ---------- launch ----------
extern "C" void kernel_launch(void* const* d_in, const int* in_sizes, int n_in,
                              void* d_out, int out_size)
{
    (void)in_sizes; (void)out_size;
    if (n_in < 8) return;

    const float* x  = (const float*)d_in[0];
    const float* w3 = (const float*)d_in[1];
    const float* b3 = (const float*)d_in[2];
    const float* w5 = (const float*)d_in[3];
    const float* b5 = (const float*)d_in[4];
    const float* w7 = (const float*)d_in[5];
    const float* b7 = (const float*)d_in[6];
    const float* wp = (const float*)d_in[7];
    float* out = (float*)d_out;

    __nv_bfloat16 *p_xh, *p_xl, *p_w3h, *p_w3l, *p_w5h, *p_w5l, *p_w7h, *p_w7l,
                  *p_wph, *p_wpl, *p_aoh, *p_aol;
    float *p_q, *p_k, *p_v;
    cudaGetSymbolAddress((void**)&p_xh,  g_xh);  cudaGetSymbolAddress((void**)&p_xl,  g_xl);
    cudaGetSymbolAddress((void**)&p_w3h, g_w3h); cudaGetSymbolAddress((void**)&p_w3l, g_w3l);
    cudaGetSymbolAddress((void**)&p_w5h, g_w5h); cudaGetSymbolAddress((void**)&p_w5l, g_w5l);
    cudaGetSymbolAddress((void**)&p_w7h, g_w7h); cudaGetSymbolAddress((void**)&p_w7l, g_w7l);
    cudaGetSymbolAddress((void**)&p_wph, g_wph); cudaGetSymbolAddress((void**)&p_wpl, g_wpl);
    cudaGetSymbolAddress((void**)&p_aoh, g_aoh); cudaGetSymbolAddress((void**)&p_aol, g_aol);
    cudaGetSymbolAddress((void**)&p_q, g_q);
    cudaGetSymbolAddress((void**)&p_k, g_k);
    cudaGetSymbolAddress((void**)&p_v, g_v);

    const int CONV_SMEM = 2 * 65536;   // 128 KB (double-buffered stages; also epilogue stage)
    cudaFuncSetAttribute(conv_mma<1, true>,  cudaFuncAttributeMaxDynamicSharedMemorySize, CONV_SMEM);
    cudaFuncSetAttribute(conv_mma<3, true>,  cudaFuncAttributeMaxDynamicSharedMemorySize, CONV_SMEM);
    cudaFuncSetAttribute(conv_mma<5, true>,  cudaFuncAttributeMaxDynamicSharedMemorySize, CONV_SMEM);
    cudaFuncSetAttribute(conv_mma<1, false>, cudaFuncAttributeMaxDynamicSharedMemorySize, CONV_SMEM);
    cudaFuncSetAttribute(attn_kernel, cudaFuncAttributeMaxDynamicSharedMemorySize, 131072);

    // bf16 hi/lo splits
    split_x<<<8192, 256>>>(x, p_xh, p_xl);
    split_w<<<1 * 256, 256>>>(w3, p_w3h, p_w3l, 1);
    split_w<<<9 * 256, 256>>>(w5, p_w5h, p_w5l, 9);
    split_w<<<25 * 256, 256>>>(w7, p_w7h, p_w7l, 25);
    split_w<<<1 * 256, 256>>>(wp, p_wph, p_wpl, 1);

    dim3 grid(2, 64);
    // q: 1x1 (w3), v: 3x3 (w5), k: 5x5 (w7) — names match the reference
    conv_mma<1, true><<<grid, 256, CONV_SMEM>>>(p_xh, p_xl, p_w3h, p_w3l, b3, p_q);
    conv_mma<3, true><<<grid, 256, CONV_SMEM>>>(p_xh, p_xl, p_w5h, p_w5l, b5, p_v);
    conv_mma<5, true><<<grid, 256, CONV_SMEM>>>(p_xh, p_xl, p_w7h, p_w7l, b7, p_k);

    attn_kernel<<<128, 512, 131072>>>(p_q, p_k, p_v, p_aoh, p_aol);

    conv_mma<1, false><<<grid, 256, CONV_SMEM>>>(p_aoh, p_aol, p_wph, p_wpl, nullptr, out);
}